// round 2
// baseline (speedup 1.0000x reference)
#include <cuda_runtime.h>
#include <math_constants.h>

// CenterNet decode, sm_100a.
// Inputs: d_in[0]=fmap f32 [32,80,128,128], d_in[1]=wh f32 [32,2,128,128],
//         d_in[2]=reg f32 [32,2,128,128], d_in[3]=K (int, =100)
// Output: f32, concat( bboxes[32,100,4], scores[32,100,1], clses[32,100,1] ) = 19200

#define NB 32
#define NC 80
#define NH 128
#define NW 128
#define NHW (NH * NW)      // 16384
#define NK 100
#define CK (NC * NK)       // 8000
#define CAP 4096           // max NMS survivors per (b,c): strict kings-graph independent set <= 4096

// scratch (allowed: __device__ globals, no allocation)
__device__ float g_score[NB * CK];
__device__ int   g_sidx[NB * CK];

extern __shared__ unsigned long long s_keys[];

// key packs (value desc, index asc) into a single descending-sortable u64.
// value >= 0 always (post-sigmoid heatmap * keep), so float bits are order-preserving.
__device__ __forceinline__ unsigned long long pack_key(float v, int idx) {
    return ((unsigned long long)__float_as_uint(v) << 32) | (unsigned)(65535 - idx);
}

__device__ __forceinline__ void bitonic_sort_desc(unsigned long long* keys, int n, int tid, int nthreads) {
    // n must be a power of two; sorts descending by u64 key
    for (int k = 2; k <= n; k <<= 1) {
        for (int j = k >> 1; j > 0; j >>= 1) {
            for (int i = tid; i < n; i += nthreads) {
                int l = i ^ j;
                if (l > i) {
                    unsigned long long a = keys[i];
                    unsigned long long b = keys[l];
                    bool desc = ((i & k) == 0);
                    if (desc ? (a < b) : (a > b)) {
                        keys[i] = b;
                        keys[l] = a;
                    }
                }
            }
            __syncthreads();
        }
    }
}

// ---------------------------------------------------------------------------
// Kernel 1: per-(b,c) pseudo-NMS + top-100. Grid = B*C = 2560 blocks.
// ---------------------------------------------------------------------------
__global__ void __launch_bounds__(512) k_topk_per_class(const float* __restrict__ fmap) {
    __shared__ int s_cnt;
    const int bc = blockIdx.x;
    const float* __restrict__ f = fmap + (size_t)bc * NHW;
    const int tid = threadIdx.x;
    const int nth = blockDim.x;

    if (tid == 0) s_cnt = 0;
    __syncthreads();

    // NMS: keep p iff f[p] >= all in-bounds 8-neighbors (matches fmax==fmap with -inf pad)
    for (int p = tid; p < NHW; p += nth) {
        const float v = __ldg(f + p);
        const int y = p >> 7;
        const int x = p & 127;
        float nm = -CUDART_INF_F;
        const bool ym = (y > 0), yp = (y < NH - 1);
        const bool xm = (x > 0), xp = (x < NW - 1);
        if (ym) {
            const float* r = f + p - NW;
            if (xm) nm = fmaxf(nm, __ldg(r - 1));
            nm = fmaxf(nm, __ldg(r));
            if (xp) nm = fmaxf(nm, __ldg(r + 1));
        }
        if (xm) nm = fmaxf(nm, __ldg(f + p - 1));
        if (xp) nm = fmaxf(nm, __ldg(f + p + 1));
        if (yp) {
            const float* r = f + p + NW;
            if (xm) nm = fmaxf(nm, __ldg(r - 1));
            nm = fmaxf(nm, __ldg(r));
            if (xp) nm = fmaxf(nm, __ldg(r + 1));
        }
        if (v >= nm && v > 0.0f) {
            int pos = atomicAdd(&s_cnt, 1);
            if (pos < CAP) s_keys[pos] = pack_key(v, p);
        }
    }
    __syncthreads();

    int n = s_cnt;
    if (n > CAP) n = CAP;
    int npad = 128;                     // >= NK, power of two
    while (npad < n) npad <<= 1;        // <= CAP
    for (int i = n + tid; i < npad; i += nth) s_keys[i] = 0ULL;
    __syncthreads();

    bitonic_sort_desc(s_keys, npad, tid, nth);

    for (int k = tid; k < NK; k += nth) {
        unsigned long long key = s_keys[k];
        float sc;
        int idx;
        if (key == 0ULL) { sc = 0.0f; idx = 0; }
        else {
            sc = __uint_as_float((unsigned)(key >> 32));
            idx = 65535 - (int)(key & 0xFFFFFFFFu);
        }
        g_score[(size_t)bc * NK + k] = sc;
        g_sidx[(size_t)bc * NK + k] = idx;
    }
}

// ---------------------------------------------------------------------------
// Kernel 2: per-batch global top-100 over C*K=8000 + decode boxes. Grid = B.
// ---------------------------------------------------------------------------
__global__ void __launch_bounds__(512) k_topk_global(const float* __restrict__ wh,
                                                     const float* __restrict__ reg,
                                                     float* __restrict__ out) {
    const int b = blockIdx.x;
    const int tid = threadIdx.x;
    const int nth = blockDim.x;
    const int N2 = 8192;

    for (int j = tid; j < N2; j += nth) {
        unsigned long long key = 0ULL;
        if (j < CK) {
            float sc = g_score[(size_t)b * CK + j];
            key = ((unsigned long long)__float_as_uint(sc) << 32) | (unsigned)(65535 - j);
        }
        s_keys[j] = key;
    }
    __syncthreads();

    bitonic_sort_desc(s_keys, N2, tid, nth);

    const float* __restrict__ whb = wh + (size_t)b * 2 * NHW;
    const float* __restrict__ rgb = reg + (size_t)b * 2 * NHW;

    for (int k = tid; k < NK; k += nth) {
        unsigned long long key = s_keys[k];
        float sc = __uint_as_float((unsigned)(key >> 32));
        int j = 65535 - (int)(key & 0xFFFFFFFFu);

        float bx0 = 0.f, by0 = 0.f, bx1 = 0.f, by1 = 0.f, cls = 0.f;
        if (j >= 0 && j < CK && key != 0ULL) {
            int c = j / NK;
            int sp = g_sidx[(size_t)b * CK + j];
            float ys = (float)(sp >> 7);
            float xs = (float)(sp & 127);
            float rx = __ldg(rgb + sp);
            float ry = __ldg(rgb + NHW + sp);
            float w0 = __ldg(whb + sp);
            float h0 = __ldg(whb + NHW + sp);
            float xc = xs + rx;
            float yc = ys + ry;
            float hw2 = 0.5f * w0;
            float hh2 = 0.5f * h0;
            bx0 = xc - hw2; by0 = yc - hh2; bx1 = xc + hw2; by1 = yc + hh2;
            cls = (float)c;
        } else {
            sc = 0.f;
        }

        size_t bb = ((size_t)b * NK + k) * 4;
        out[bb + 0] = bx0;
        out[bb + 1] = by0;
        out[bb + 2] = bx1;
        out[bb + 3] = by1;
        out[(size_t)NB * NK * 4 + (size_t)b * NK + k] = sc;
        out[(size_t)NB * NK * 5 + (size_t)b * NK + k] = cls;
    }
}

extern "C" void kernel_launch(void* const* d_in, const int* in_sizes, int n_in,
                              void* d_out, int out_size) {
    const float* fmap = (const float*)d_in[0];
    const float* wh   = (const float*)d_in[1];
    const float* reg  = (const float*)d_in[2];
    float* out = (float*)d_out;

    static bool attr_done = false;
    if (!attr_done) {
        cudaFuncSetAttribute(k_topk_global, cudaFuncAttributeMaxDynamicSharedMemorySize,
                             8192 * sizeof(unsigned long long));
        cudaFuncSetAttribute(k_topk_per_class, cudaFuncAttributeMaxDynamicSharedMemorySize,
                             CAP * sizeof(unsigned long long));
        attr_done = true;
    }

    k_topk_per_class<<<NB * NC, 512, CAP * sizeof(unsigned long long)>>>(fmap);
    k_topk_global<<<NB, 512, 8192 * sizeof(unsigned long long)>>>(wh, reg, out);
}